// round 1
// baseline (speedup 1.0000x reference)
#include <cuda_runtime.h>
#include <cstdint>

// SparseAdam: segment-mean of grad by idx, then Adam update on touched rows.
//
// Inputs (metadata order):
//   0: idx        int32  [N]
//   1: grad       f32    [N, 128]
//   2: emb        f32    [V, 128]
//   3: state_step f32    [V]
//   4: state_mem  f32    [V, 128]
//   5: state_pow  f32    [V, 128]
// Output (f32, concatenated): new_emb [V,128] | new_step [V] | new_mem [V,128] | new_pow [V,128]
//
// Strategy: accumulate segment counts into out_step region and segment grad-sums
// into out_pow region (both zeroed first), so no device scratch is needed.
// Final pass converts in place. Everything is HBM-streaming; scatter uses
// red.global.add.v4.f32 to keep the LSU/REDG issue rate off the critical path.

#define DD 128

static __device__ __forceinline__ void red_add_v4(float* p, float4 g) {
    asm volatile("red.global.add.v4.f32 [%0], {%1, %2, %3, %4};"
                 :: "l"(p), "f"(g.x), "f"(g.y), "f"(g.z), "f"(g.w)
                 : "memory");
}

static __device__ __forceinline__ void red_add_f32(float* p, float v) {
    asm volatile("red.global.add.f32 [%0], %1;"
                 :: "l"(p), "f"(v)
                 : "memory");
}

// ---------------------------------------------------------------------------
// Pass 1: zero the accumulator regions (out_pow: V*128 floats, out_step: V).
// ---------------------------------------------------------------------------
__global__ void sadam_zero_k(float4* __restrict__ pow_out,
                             float*  __restrict__ step_out, int V) {
    const long n4 = (long)V * (DD / 4);
    const long stride = (long)gridDim.x * blockDim.x;
    const float4 z = make_float4(0.f, 0.f, 0.f, 0.f);
    for (long i = (long)blockIdx.x * blockDim.x + threadIdx.x; i < n4; i += stride)
        pow_out[i] = z;
    for (long i = (long)blockIdx.x * blockDim.x + threadIdx.x; i < V; i += stride)
        step_out[i] = 0.f;
}

// ---------------------------------------------------------------------------
// Pass 2: scatter. One warp per grad row. Lane l handles 4 floats (float4).
// gsum accumulates into out_pow region; counts accumulate into out_step region.
// ---------------------------------------------------------------------------
__global__ void sadam_scatter_k(const int*    __restrict__ idx,
                                const float4* __restrict__ grad,
                                float* __restrict__ cnt_out,   // = out_step region
                                float* __restrict__ gsum_out,  // = out_pow region
                                int N) {
    const int gtid = blockIdx.x * blockDim.x + threadIdx.x;
    const int row  = gtid >> 5;
    const int lane = gtid & 31;
    if (row >= N) return;

    int v;
    if (lane == 0) v = __ldg(idx + row);
    v = __shfl_sync(0xffffffffu, v, 0);

    float4 g = __ldg(grad + (size_t)row * (DD / 4) + lane);
    red_add_v4(gsum_out + (size_t)v * DD + lane * 4, g);
    if (lane == 0) red_add_f32(cnt_out + v, 1.0f);
}

// ---------------------------------------------------------------------------
// Pass 3: per-vocab-row Adam update. One warp per row, float4 per lane.
// Reads cnt from out_step and gsum from out_pow, overwrites both with finals.
// ---------------------------------------------------------------------------
__global__ void sadam_update_k(const float4* __restrict__ emb,
                               const float*  __restrict__ step_in,
                               const float4* __restrict__ mem,
                               const float4* __restrict__ pw,
                               float4* __restrict__ out_emb,
                               float*  __restrict__ out_step,
                               float4* __restrict__ out_mem,
                               float4* __restrict__ out_pow,
                               int V) {
    const long gtid = (long)blockIdx.x * blockDim.x + threadIdx.x;
    const long total = (long)V * 32;
    if (gtid >= total) return;
    const long row  = gtid >> 5;
    const int  lane = (int)(gtid & 31);
    const long i4   = row * (DD / 4) + lane;

    const float cnt = out_step[row];       // accumulated count (read before store)
    const float st  = __ldg(step_in + row);

    float4 gs = out_pow[i4];               // accumulated gsum (read before store)
    float4 e  = __ldg(emb + i4);
    float4 m  = __ldg(mem + i4);
    float4 p  = __ldg(pw  + i4);

    float4 ne, nm, np;
    float  nstep;

    if (cnt > 0.f) {
        nstep = st + 1.f;
        const float inv = 1.f / cnt;
        // bias corrections (row-uniform)
        const float d1 = 1.f - exp2f(nstep * -0.15200309344504997f);   // 1 - 0.9^nstep
        const float d2 = 1.f - exp2f(nstep * -0.0014434169010128458f); // 1 - 0.999^nstep
        const float c1 = 0.001f / d1;   // LR / d1
        const float id2 = 1.f / d2;

        #define ADAM1(GS, M, P, E, NM, NP, NE)                                  \
        {                                                                        \
            float g = (GS) * inv;                                                \
            NM = 0.9f * (M) + 0.1f * g;                                          \
            NP = 0.999f * (P) + 0.001f * (g * g);                                \
            float stdv = c1 * NM / (sqrtf(NP * id2) + 1e-8f);                    \
            NE = (E) - stdv;                                                     \
        }
        ADAM1(gs.x, m.x, p.x, e.x, nm.x, np.x, ne.x)
        ADAM1(gs.y, m.y, p.y, e.y, nm.y, np.y, ne.y)
        ADAM1(gs.z, m.z, p.z, e.z, nm.z, np.z, ne.z)
        ADAM1(gs.w, m.w, p.w, e.w, nm.w, np.w, ne.w)
        #undef ADAM1
    } else {
        nstep = st;
        ne = e; nm = m; np = p;
    }

    out_emb[i4] = ne;
    out_mem[i4] = nm;
    out_pow[i4] = np;
    if (lane == 0) out_step[row] = nstep;
}

// ---------------------------------------------------------------------------
extern "C" void kernel_launch(void* const* d_in, const int* in_sizes, int n_in,
                              void* d_out, int out_size) {
    const int*   idx  = (const int*)  d_in[0];
    const float* grad = (const float*)d_in[1];
    const float* emb  = (const float*)d_in[2];
    const float* step = (const float*)d_in[3];
    const float* mem  = (const float*)d_in[4];
    const float* pw   = (const float*)d_in[5];

    const int N = in_sizes[0];
    const int V = in_sizes[3];

    float* out      = (float*)d_out;
    float* out_emb  = out;                          // V*128
    float* out_step = out_emb + (long)V * DD;       // V
    float* out_mem  = out_step + V;                 // V*128
    float* out_pow  = out_mem + (long)V * DD;       // V*128

    // Pass 1: zero accumulators (out_pow + out_step regions).
    sadam_zero_k<<<2048, 256>>>((float4*)out_pow, out_step, V);

    // Pass 2: scatter grad sums + counts. One warp per grad row.
    {
        const long threads = (long)N * 32;
        const int  blocks  = (int)((threads + 255) / 256);
        sadam_scatter_k<<<blocks, 256>>>(idx, (const float4*)grad,
                                         out_step, out_pow, N);
    }

    // Pass 3: Adam update over all V rows. One warp per row.
    {
        const long threads = (long)V * 32;
        const int  blocks  = (int)((threads + 255) / 256);
        sadam_update_k<<<blocks, 256>>>((const float4*)emb, step,
                                        (const float4*)mem, (const float4*)pw,
                                        (float4*)out_emb, out_step,
                                        (float4*)out_mem, (float4*)out_pow, V);
    }
}

// round 2
// speedup vs baseline: 1.1649x; 1.1649x over previous
#include <cuda_runtime.h>
#include <cstdint>

// SparseAdam via inverted index (counting sort on idx), no dense gsum buffer.
//
// Inputs: 0 idx i32[N], 1 grad f32[N,128], 2 emb f32[V,128], 3 step f32[V],
//         4 mem f32[V,128], 5 pow f32[V,128]
// Output: new_emb[V,128] | new_step[V] | new_mem[V,128] | new_pow[V,128]
//
// Index structures are tiny (4-8 MB each, L2-resident). The single update pass
// gathers grad rows per vocab row, hitting the 3.6 GB traffic floor.

#define DD 128
#define MAXE (1 << 21)          // max(N, V) safety bound
#define SCAN_CHUNK 2048         // elements per scan block (512 thr x 4)
#define MAX_SCAN_BLOCKS 1024    // MAXE / SCAN_CHUNK

__device__ int g_counts[MAXE];
__device__ int g_offsets[MAXE];
__device__ int g_cursor[MAXE];
__device__ int g_rowids[MAXE];
__device__ int g_partials[MAX_SCAN_BLOCKS];

// ---------------------------------------------------------------------------
__global__ void zero_counts_k(int V) {
    int stride = gridDim.x * blockDim.x;
    for (int i = blockIdx.x * blockDim.x + threadIdx.x; i < V; i += stride)
        g_counts[i] = 0;
}

__global__ void hist_k(const int* __restrict__ idx, int N) {
    int i = blockIdx.x * blockDim.x + threadIdx.x;
    if (i < N) atomicAdd(&g_counts[__ldg(idx + i)], 1);
}

// Scan pass 1: per-block exclusive scan of counts -> offsets (local), block
// totals -> partials. 512 threads x 4 elems = 2048 per block.
__global__ void scan1_k(int V) {
    __shared__ int sh[512];
    const int t = threadIdx.x;
    const int base = blockIdx.x * SCAN_CHUNK + t * 4;

    int a0 = 0, a1 = 0, a2 = 0, a3 = 0;
    if (base + 3 < V) {
        a0 = g_counts[base];     a1 = g_counts[base + 1];
        a2 = g_counts[base + 2]; a3 = g_counts[base + 3];
    } else {
        if (base + 0 < V) a0 = g_counts[base + 0];
        if (base + 1 < V) a1 = g_counts[base + 1];
        if (base + 2 < V) a2 = g_counts[base + 2];
        if (base + 3 < V) a3 = g_counts[base + 3];
    }
    int s = a0 + a1 + a2 + a3;
    sh[t] = s;
    __syncthreads();
    // Hillis-Steele inclusive scan over 512 entries
    #pragma unroll
    for (int d = 1; d < 512; d <<= 1) {
        int v = (t >= d) ? sh[t - d] : 0;
        __syncthreads();
        sh[t] += v;
        __syncthreads();
    }
    int excl = sh[t] - s;            // exclusive prefix for this thread
    if (t == 511) g_partials[blockIdx.x] = sh[511];

    if (base + 0 < V) g_offsets[base + 0] = excl;
    if (base + 1 < V) g_offsets[base + 1] = excl + a0;
    if (base + 2 < V) g_offsets[base + 2] = excl + a0 + a1;
    if (base + 3 < V) g_offsets[base + 3] = excl + a0 + a1 + a2;
}

// Scan pass 2: single-block exclusive scan of partials (nb <= 1024).
__global__ void scan2_k(int nb) {
    __shared__ int sh[MAX_SCAN_BLOCKS];
    const int t = threadIdx.x;
    int v = (t < nb) ? g_partials[t] : 0;
    sh[t] = v;
    __syncthreads();
    #pragma unroll
    for (int d = 1; d < MAX_SCAN_BLOCKS; d <<= 1) {
        int u = (t >= d) ? sh[t - d] : 0;
        __syncthreads();
        sh[t] += u;
        __syncthreads();
    }
    if (t < nb) g_partials[t] = sh[t] - v;   // exclusive
}

// Scan pass 3: add block prefixes, init cursor copy.
__global__ void scan3_k(int V) {
    int stride = gridDim.x * blockDim.x;
    for (int i = blockIdx.x * blockDim.x + threadIdx.x; i < V; i += stride) {
        int off = g_offsets[i] + g_partials[i / SCAN_CHUNK];
        g_offsets[i] = off;
        g_cursor[i]  = off;
    }
}

__global__ void scatter_ids_k(const int* __restrict__ idx, int N) {
    int i = blockIdx.x * blockDim.x + threadIdx.x;
    if (i < N) {
        int v = __ldg(idx + i);
        int pos = atomicAdd(&g_cursor[v], 1);
        g_rowids[pos] = i;
    }
}

// ---------------------------------------------------------------------------
// Update: one warp per vocab row. Gather this row's grad contributions via the
// inverted index, compute mean + Adam in registers, write all outputs.
// ---------------------------------------------------------------------------
__global__ void sadam_update_k(const float4* __restrict__ grad,
                               const float4* __restrict__ emb,
                               const float*  __restrict__ step_in,
                               const float4* __restrict__ mem,
                               const float4* __restrict__ pw,
                               float4* __restrict__ out_emb,
                               float*  __restrict__ out_step,
                               float4* __restrict__ out_mem,
                               float4* __restrict__ out_pow,
                               int V) {
    const long gtid = (long)blockIdx.x * blockDim.x + threadIdx.x;
    const long row  = gtid >> 5;
    if (row >= V) return;
    const int  lane = (int)(gtid & 31);
    const long i4   = row * (DD / 4) + lane;

    const int   cnt = g_counts[row];
    const float st  = __ldg(step_in + row);

    float4 e = __ldg(emb + i4);
    float4 m = __ldg(mem + i4);
    float4 p = __ldg(pw  + i4);

    float4 ne, nm, np;
    float  nstep;

    if (cnt > 0) {
        const int start = g_offsets[row];
        float4 gs = make_float4(0.f, 0.f, 0.f, 0.f);
        for (int j = 0; j < cnt; j++) {
            int r = g_rowids[start + j];                 // lane-uniform (L1 bcast)
            float4 g = __ldg(grad + (long)r * (DD / 4) + lane);
            gs.x += g.x; gs.y += g.y; gs.z += g.z; gs.w += g.w;
        }
        nstep = st + 1.f;
        const float inv = 1.f / (float)cnt;
        const float d1 = 1.f - exp2f(nstep * -0.15200309344504997f);   // 1-0.9^s
        const float d2 = 1.f - exp2f(nstep * -0.0014434169010128458f); // 1-0.999^s
        const float c1  = 0.001f / d1;
        const float id2 = 1.f / d2;

        #define ADAM1(GS, M, P, E, NM, NP, NE)                       \
        {                                                             \
            float g = (GS) * inv;                                     \
            NM = 0.9f * (M) + 0.1f * g;                               \
            NP = 0.999f * (P) + 0.001f * (g * g);                     \
            float stdv = c1 * NM / (sqrtf(NP * id2) + 1e-8f);         \
            NE = (E) - stdv;                                          \
        }
        ADAM1(gs.x, m.x, p.x, e.x, nm.x, np.x, ne.x)
        ADAM1(gs.y, m.y, p.y, e.y, nm.y, np.y, ne.y)
        ADAM1(gs.z, m.z, p.z, e.z, nm.z, np.z, ne.z)
        ADAM1(gs.w, m.w, p.w, e.w, nm.w, np.w, ne.w)
        #undef ADAM1
    } else {
        nstep = st;
        ne = e; nm = m; np = p;
    }

    out_emb[i4] = ne;
    out_mem[i4] = nm;
    out_pow[i4] = np;
    if (lane == 0) out_step[row] = nstep;
}

// ---------------------------------------------------------------------------
extern "C" void kernel_launch(void* const* d_in, const int* in_sizes, int n_in,
                              void* d_out, int out_size) {
    const int*   idx  = (const int*)  d_in[0];
    const float* grad = (const float*)d_in[1];
    const float* emb  = (const float*)d_in[2];
    const float* step = (const float*)d_in[3];
    const float* mem  = (const float*)d_in[4];
    const float* pw   = (const float*)d_in[5];

    const int N = in_sizes[0];
    const int V = in_sizes[3];

    float* out      = (float*)d_out;
    float* out_emb  = out;
    float* out_step = out_emb + (long)V * DD;
    float* out_mem  = out_step + V;
    float* out_pow  = out_mem + (long)V * DD;

    // Build inverted index (all L2-resident, ~40us total).
    zero_counts_k<<<1024, 256>>>(V);
    hist_k<<<(N + 255) / 256, 256>>>(idx, N);
    const int nb = (V + SCAN_CHUNK - 1) / SCAN_CHUNK;
    scan1_k<<<nb, 512>>>(V);
    scan2_k<<<1, MAX_SCAN_BLOCKS>>>(nb);
    scan3_k<<<1024, 256>>>(V);
    scatter_ids_k<<<(N + 255) / 256, 256>>>(idx, N);

    // Fused gather + Adam update (the 3.6 GB streaming pass).
    {
        const long threads = (long)V * 32;
        const int  blocks  = (int)((threads + 255) / 256);
        sadam_update_k<<<blocks, 256>>>((const float4*)grad, (const float4*)emb,
                                        step, (const float4*)mem, (const float4*)pw,
                                        (float4*)out_emb, out_step,
                                        (float4*)out_mem, (float4*)out_pow, V);
    }
}

// round 3
// speedup vs baseline: 1.1773x; 1.0106x over previous
#include <cuda_runtime.h>
#include <cstdint>

// SparseAdam via inverted index (counting sort) + single fused streaming pass.
//
// Inputs: 0 idx i32[N], 1 grad f32[N,128], 2 emb f32[V,128], 3 step f32[V],
//         4 mem f32[V,128], 5 pow f32[V,128]
// Output: new_emb[V,128] | new_step[V] | new_mem[V,128] | new_pow[V,128]
//
// Pipeline (5 graph nodes):
//   memset(counts+desc) -> hist -> lookback-scan -> scatter_ids -> update
// Index arrays are L2-resident; the update pass streams the 3.6 GB floor with
// evict-first cache hints so the index stays hot in L2.

#define DD 128
#define MAXE (1 << 21)
#define SCAN_BS 256
#define SCAN_PT 16
#define SCAN_TILE (SCAN_BS * SCAN_PT)   // 4096
#define MAX_SCAN_BLOCKS 1024

__device__ int g_counts[MAXE];
__device__ int g_offsets[MAXE];
__device__ int g_rowids[MAXE];
__device__ unsigned long long g_desc[MAX_SCAN_BLOCKS];

// ---------------------------------------------------------------------------
// Histogram over idx (int4-vectorized).
// ---------------------------------------------------------------------------
__global__ void hist_k(const int* __restrict__ idx, int N) {
    const int n4 = N >> 2;
    const int stride = gridDim.x * blockDim.x;
    const int4* idx4 = (const int4*)idx;
    for (int i = blockIdx.x * blockDim.x + threadIdx.x; i < n4; i += stride) {
        int4 v = __ldg(idx4 + i);
        atomicAdd(&g_counts[v.x], 1);
        atomicAdd(&g_counts[v.y], 1);
        atomicAdd(&g_counts[v.z], 1);
        atomicAdd(&g_counts[v.w], 1);
    }
    // tail
    for (int i = (n4 << 2) + blockIdx.x * blockDim.x + threadIdx.x; i < N; i += stride)
        atomicAdd(&g_counts[__ldg(idx + i)], 1);
}

// ---------------------------------------------------------------------------
// Single-pass exclusive scan with decoupled lookback.
// counts -> offsets. Grid must be ceil(V / SCAN_TILE) blocks of SCAN_BS.
// g_desc must be zeroed before launch (state 0 = invalid).
// ---------------------------------------------------------------------------
__global__ void scan_lb_k(int V) {
    const int bid = blockIdx.x;
    const int t = threadIdx.x;
    const int lane = t & 31;
    const int wid = t >> 5;
    const int base = bid * SCAN_TILE + t * SCAN_PT;

    // Sequential local scan of 16 elems in registers.
    int v[SCAN_PT];
    int s = 0;
    #pragma unroll
    for (int i = 0; i < SCAN_PT; i++) {
        int x = (base + i < V) ? g_counts[base + i] : 0;
        v[i] = s;
        s += x;
    }

    // Warp-inclusive scan of thread sums.
    int incl = s;
    #pragma unroll
    for (int d = 1; d < 32; d <<= 1) {
        int u = __shfl_up_sync(0xffffffffu, incl, d);
        if (lane >= d) incl += u;
    }

    __shared__ int wsum[SCAN_BS / 32];
    __shared__ int woff[SCAN_BS / 32];
    __shared__ int sh_total;
    __shared__ int sh_prefix;
    if (lane == 31) wsum[wid] = incl;
    __syncthreads();
    if (t < SCAN_BS / 32) {            // 8 threads of warp 0
        int x = wsum[t];
        int ss = x;
        #pragma unroll
        for (int d = 1; d < SCAN_BS / 32; d <<= 1) {
            int u = __shfl_up_sync(0xffu, ss, d);
            if (t >= d) ss += u;
        }
        woff[t] = ss - x;
        if (t == (SCAN_BS / 32) - 1) sh_total = ss;
    }
    __syncthreads();
    const int total = sh_total;

    // Publish aggregate / do lookback (thread 0).
    if (t == 0) {
        if (bid == 0) {
            atomicExch(&g_desc[0],
                       (2ULL << 62) | (unsigned long long)(unsigned)total);
            sh_prefix = 0;
        } else {
            atomicExch(&g_desc[bid],
                       (1ULL << 62) | (unsigned long long)(unsigned)total);
            int prefix = 0;
            int j = bid - 1;
            while (true) {
                unsigned long long d;
                do {
                    d = atomicAdd(&g_desc[j], 0ULL);
                } while ((d >> 62) == 0ULL);
                prefix += (int)(unsigned)(d & 0xffffffffULL);
                if ((d >> 62) == 2ULL) break;
                j--;
            }
            atomicExch(&g_desc[bid],
                       (2ULL << 62) | (unsigned long long)(unsigned)(total + prefix));
            sh_prefix = prefix;
        }
    }
    __syncthreads();

    const int excl_thread = sh_prefix + woff[wid] + (incl - s);
    #pragma unroll
    for (int i = 0; i < SCAN_PT; i++)
        if (base + i < V) g_offsets[base + i] = excl_thread + v[i];
}

// ---------------------------------------------------------------------------
// Scatter row-ids. Bumps g_offsets; update recovers start = offsets - counts.
// ---------------------------------------------------------------------------
__global__ void scatter_ids_k(const int* __restrict__ idx, int N) {
    const int n4 = N >> 2;
    const int stride = gridDim.x * blockDim.x;
    const int4* idx4 = (const int4*)idx;
    for (int i = blockIdx.x * blockDim.x + threadIdx.x; i < n4; i += stride) {
        int4 v = __ldg(idx4 + i);
        int b = i << 2;
        g_rowids[atomicAdd(&g_offsets[v.x], 1)] = b;
        g_rowids[atomicAdd(&g_offsets[v.y], 1)] = b + 1;
        g_rowids[atomicAdd(&g_offsets[v.z], 1)] = b + 2;
        g_rowids[atomicAdd(&g_offsets[v.w], 1)] = b + 3;
    }
    for (int i = (n4 << 2) + blockIdx.x * blockDim.x + threadIdx.x; i < N; i += stride)
        g_rowids[atomicAdd(&g_offsets[__ldg(idx + i)], 1)] = i;
}

// ---------------------------------------------------------------------------
// Fused gather + Adam update. One warp per vocab row, float4 per lane.
// Streaming data uses evict-first hints to keep index arrays resident in L2.
// ---------------------------------------------------------------------------
__global__ void sadam_update_k(const float4* __restrict__ grad,
                               const float4* __restrict__ emb,
                               const float*  __restrict__ step_in,
                               const float4* __restrict__ mem,
                               const float4* __restrict__ pw,
                               float4* __restrict__ out_emb,
                               float*  __restrict__ out_step,
                               float4* __restrict__ out_mem,
                               float4* __restrict__ out_pow,
                               int V) {
    const long gtid = (long)blockIdx.x * blockDim.x + threadIdx.x;
    const long row  = gtid >> 5;
    if (row >= V) return;
    const int  lane = (int)(gtid & 31);
    const long i4   = row * (DD / 4) + lane;

    const int   cnt = g_counts[row];
    const float st  = __ldg(step_in + row);

    float4 e = __ldcs(emb + i4);
    float4 m = __ldcs(mem + i4);
    float4 p = __ldcs(pw  + i4);

    float4 ne, nm, np;
    float  nstep;

    if (cnt > 0) {
        const int start = g_offsets[row] - cnt;   // scatter bumped offsets by cnt
        float4 gs = make_float4(0.f, 0.f, 0.f, 0.f);
        for (int j = 0; j < cnt; j++) {
            int r = g_rowids[start + j];          // lane-uniform broadcast
            float4 g = __ldcs(grad + (long)r * (DD / 4) + lane);
            gs.x += g.x; gs.y += g.y; gs.z += g.z; gs.w += g.w;
        }
        nstep = st + 1.f;
        const float inv = 1.f / (float)cnt;
        const float d1 = 1.f - exp2f(nstep * -0.15200309344504997f);   // 1-0.9^s
        const float d2 = 1.f - exp2f(nstep * -0.0014434169010128458f); // 1-0.999^s
        const float c1  = 0.001f / d1;
        const float id2 = 1.f / d2;

        #define ADAM1(GS, M, P, E, NM, NP, NE)                       \
        {                                                             \
            float g = (GS) * inv;                                     \
            NM = 0.9f * (M) + 0.1f * g;                               \
            NP = 0.999f * (P) + 0.001f * (g * g);                     \
            float stdv = c1 * NM / (sqrtf(NP * id2) + 1e-8f);         \
            NE = (E) - stdv;                                          \
        }
        ADAM1(gs.x, m.x, p.x, e.x, nm.x, np.x, ne.x)
        ADAM1(gs.y, m.y, p.y, e.y, nm.y, np.y, ne.y)
        ADAM1(gs.z, m.z, p.z, e.z, nm.z, np.z, ne.z)
        ADAM1(gs.w, m.w, p.w, e.w, nm.w, np.w, ne.w)
        #undef ADAM1
    } else {
        nstep = st;
        ne = e; nm = m; np = p;
    }

    __stcs(out_emb + i4, ne);
    __stcs(out_mem + i4, nm);
    __stcs(out_pow + i4, np);
    if (lane == 0) out_step[row] = nstep;
}

// ---------------------------------------------------------------------------
extern "C" void kernel_launch(void* const* d_in, const int* in_sizes, int n_in,
                              void* d_out, int out_size) {
    const int*   idx  = (const int*)  d_in[0];
    const float* grad = (const float*)d_in[1];
    const float* emb  = (const float*)d_in[2];
    const float* step = (const float*)d_in[3];
    const float* mem  = (const float*)d_in[4];
    const float* pw   = (const float*)d_in[5];

    const int N = in_sizes[0];
    const int V = in_sizes[3];

    float* out      = (float*)d_out;
    float* out_emb  = out;
    float* out_step = out_emb + (long)V * DD;
    float* out_mem  = out_step + V;
    float* out_pow  = out_mem + (long)V * DD;

    // Zero counts + lookback descriptors (device-symbol addresses).
    void* counts_ptr = nullptr;
    void* desc_ptr   = nullptr;
    cudaGetSymbolAddress(&counts_ptr, g_counts);
    cudaGetSymbolAddress(&desc_ptr, g_desc);
    cudaMemsetAsync(counts_ptr, 0, (size_t)V * sizeof(int));
    cudaMemsetAsync(desc_ptr, 0, sizeof(unsigned long long) * MAX_SCAN_BLOCKS);

    hist_k<<<592, 256>>>(idx, N);

    const int nb = (V + SCAN_TILE - 1) / SCAN_TILE;
    scan_lb_k<<<nb, SCAN_BS>>>(V);

    scatter_ids_k<<<592, 256>>>(idx, N);

    {
        const long threads = (long)V * 32;
        const int  blocks  = (int)((threads + 255) / 256);
        sadam_update_k<<<blocks, 256>>>((const float4*)grad, (const float4*)emb,
                                        step, (const float4*)mem, (const float4*)pw,
                                        (float4*)out_emb, out_step,
                                        (float4*)out_mem, (float4*)out_pow, V);
    }
}